// round 16
// baseline (speedup 1.0000x reference)
#include <cuda_runtime.h>
#include <math.h>

#define NN   8192
#define DD   512
#define KTOP 20

// Scratch (allocation-free: __device__ globals)
__device__ float g_Q[NN * DD];                 // 16 MB, pre-scaled by 1/sqrt(D)
__device__ float g_Km[NN * DD];                // 16 MB
__device__ float g_logits[(size_t)NN * NN];    // 256 MB

// ---------------------------------------------------------------------------
// NT sgemm core: C[i,j] = sum_k A[i,k]*B[j,k], 128x128 tile, BK=16,
// 256 threads, 8x8 micro-tile per thread.
// ---------------------------------------------------------------------------

// Projection: C = (h @ W^T) * alpha, writes g_Q (which=0) or g_Km (which=1)
__global__ __launch_bounds__(256, 2)
void proj_kernel(const float* __restrict__ A, const float* __restrict__ B,
                 float alpha, int which)
{
    __shared__ __align__(16) float As[16][128];
    __shared__ __align__(16) float Bs[16][128];
    const int K  = DD;
    const int Nc = DD;
    int tid = threadIdx.x;
    int m0 = blockIdx.y * 128;
    int n0 = blockIdx.x * 128;
    int tr = (tid >> 4) << 3;      // 0..120
    int tc = (tid & 15) << 3;      // 0..120
    int lr = tid >> 2;             // 0..63
    int lk = (tid & 3) << 2;       // 0,4,8,12

    float acc[8][8];
#pragma unroll
    for (int i = 0; i < 8; i++)
#pragma unroll
        for (int j = 0; j < 8; j++) acc[i][j] = 0.f;

    const float* Ap = A + (size_t)(m0 + lr) * K + lk;
    const float* Bp = B + (size_t)(n0 + lr) * K + lk;

    for (int k0 = 0; k0 < K; k0 += 16) {
        float4 a0 = *(const float4*)(Ap + k0);
        float4 a1 = *(const float4*)(Ap + (size_t)64 * K + k0);
        float4 b0 = *(const float4*)(Bp + k0);
        float4 b1 = *(const float4*)(Bp + (size_t)64 * K + k0);
        As[lk+0][lr]    = a0.x; As[lk+1][lr]    = a0.y; As[lk+2][lr]    = a0.z; As[lk+3][lr]    = a0.w;
        As[lk+0][lr+64] = a1.x; As[lk+1][lr+64] = a1.y; As[lk+2][lr+64] = a1.z; As[lk+3][lr+64] = a1.w;
        Bs[lk+0][lr]    = b0.x; Bs[lk+1][lr]    = b0.y; Bs[lk+2][lr]    = b0.z; Bs[lk+3][lr]    = b0.w;
        Bs[lk+0][lr+64] = b1.x; Bs[lk+1][lr+64] = b1.y; Bs[lk+2][lr+64] = b1.z; Bs[lk+3][lr+64] = b1.w;
        __syncthreads();
#pragma unroll
        for (int kk = 0; kk < 16; kk++) {
            float4 av0 = *(const float4*)&As[kk][tr];
            float4 av1 = *(const float4*)&As[kk][tr + 4];
            float4 bv0 = *(const float4*)&Bs[kk][tc];
            float4 bv1 = *(const float4*)&Bs[kk][tc + 4];
            float a[8] = {av0.x, av0.y, av0.z, av0.w, av1.x, av1.y, av1.z, av1.w};
            float b[8] = {bv0.x, bv0.y, bv0.z, bv0.w, bv1.x, bv1.y, bv1.z, bv1.w};
#pragma unroll
            for (int i = 0; i < 8; i++)
#pragma unroll
                for (int j = 0; j < 8; j++)
                    acc[i][j] = fmaf(a[i], b[j], acc[i][j]);
        }
        __syncthreads();
    }

    float* C = which ? g_Km : g_Q;
#pragma unroll
    for (int i = 0; i < 8; i++) {
        float* crow = C + (size_t)(m0 + tr + i) * Nc + n0 + tc;
        float4 v0 = make_float4(acc[i][0]*alpha, acc[i][1]*alpha, acc[i][2]*alpha, acc[i][3]*alpha);
        float4 v1 = make_float4(acc[i][4]*alpha, acc[i][5]*alpha, acc[i][6]*alpha, acc[i][7]*alpha);
        *(float4*)(crow)     = v0;
        *(float4*)(crow + 4) = v1;
    }
}

// logits = Qs @ K^T + prior_scale*prior, diag = -inf  (Qs already /sqrt(D))
__global__ __launch_bounds__(256, 2)
void logits_kernel(const float* __restrict__ prior,
                   const float* __restrict__ prior_scale)
{
    __shared__ __align__(16) float As[16][128];
    __shared__ __align__(16) float Bs[16][128];
    const int K = DD;
    int tid = threadIdx.x;
    int m0 = blockIdx.y * 128;
    int n0 = blockIdx.x * 128;
    int tr = (tid >> 4) << 3;
    int tc = (tid & 15) << 3;
    int lr = tid >> 2;
    int lk = (tid & 3) << 2;

    float acc[8][8];
#pragma unroll
    for (int i = 0; i < 8; i++)
#pragma unroll
        for (int j = 0; j < 8; j++) acc[i][j] = 0.f;

    const float* Ap = g_Q  + (size_t)(m0 + lr) * K + lk;
    const float* Bp = g_Km + (size_t)(n0 + lr) * K + lk;

    for (int k0 = 0; k0 < K; k0 += 16) {
        float4 a0 = *(const float4*)(Ap + k0);
        float4 a1 = *(const float4*)(Ap + (size_t)64 * K + k0);
        float4 b0 = *(const float4*)(Bp + k0);
        float4 b1 = *(const float4*)(Bp + (size_t)64 * K + k0);
        As[lk+0][lr]    = a0.x; As[lk+1][lr]    = a0.y; As[lk+2][lr]    = a0.z; As[lk+3][lr]    = a0.w;
        As[lk+0][lr+64] = a1.x; As[lk+1][lr+64] = a1.y; As[lk+2][lr+64] = a1.z; As[lk+3][lr+64] = a1.w;
        Bs[lk+0][lr]    = b0.x; Bs[lk+1][lr]    = b0.y; Bs[lk+2][lr]    = b0.z; Bs[lk+3][lr]    = b0.w;
        Bs[lk+0][lr+64] = b1.x; Bs[lk+1][lr+64] = b1.y; Bs[lk+2][lr+64] = b1.z; Bs[lk+3][lr+64] = b1.w;
        __syncthreads();
#pragma unroll
        for (int kk = 0; kk < 16; kk++) {
            float4 av0 = *(const float4*)&As[kk][tr];
            float4 av1 = *(const float4*)&As[kk][tr + 4];
            float4 bv0 = *(const float4*)&Bs[kk][tc];
            float4 bv1 = *(const float4*)&Bs[kk][tc + 4];
            float a[8] = {av0.x, av0.y, av0.z, av0.w, av1.x, av1.y, av1.z, av1.w};
            float b[8] = {bv0.x, bv0.y, bv0.z, bv0.w, bv1.x, bv1.y, bv1.z, bv1.w};
#pragma unroll
            for (int i = 0; i < 8; i++)
#pragma unroll
                for (int j = 0; j < 8; j++)
                    acc[i][j] = fmaf(a[i], b[j], acc[i][j]);
        }
        __syncthreads();
    }

    float ps = *prior_scale;
#pragma unroll
    for (int i = 0; i < 8; i++) {
        int r = m0 + tr + i;
        const float* prow = prior    + (size_t)r * NN + n0 + tc;
        float*       lrow = g_logits + (size_t)r * NN + n0 + tc;
        float4 p0 = *(const float4*)(prow);
        float4 p1 = *(const float4*)(prow + 4);
        float v[8];
        v[0] = fmaf(ps, p0.x, acc[i][0]);
        v[1] = fmaf(ps, p0.y, acc[i][1]);
        v[2] = fmaf(ps, p0.z, acc[i][2]);
        v[3] = fmaf(ps, p0.w, acc[i][3]);
        v[4] = fmaf(ps, p1.x, acc[i][4]);
        v[5] = fmaf(ps, p1.y, acc[i][5]);
        v[6] = fmaf(ps, p1.z, acc[i][6]);
        v[7] = fmaf(ps, p1.w, acc[i][7]);
        int dj = r - (n0 + tc);          // diagonal position within this 8-chunk
        if (dj >= 0 && dj < 8) v[dj] = -INFINITY;
        *(float4*)(lrow)     = make_float4(v[0], v[1], v[2], v[3]);
        *(float4*)(lrow + 4) = make_float4(v[4], v[5], v[6], v[7]);
    }
}

// One CTA per row: stage row in smem, 20x block-argmax, softmax over the 20,
// zero + scatter the output row.
__global__ __launch_bounds__(256)
void topk_softmax_kernel(float* __restrict__ out)
{
    __shared__ float sv[NN];
    __shared__ float rv[256];
    __shared__ int   ri[256];
    __shared__ float tv[KTOP];
    __shared__ int   tix[KTOP];

    int row = blockIdx.x;
    int tid = threadIdx.x;
    const float* lrow = g_logits + (size_t)row * NN;
    float*       orow = out      + (size_t)row * NN;

    // stage row and zero the output row (d_out is poisoned)
    for (int j = tid; j < NN; j += 256) {
        sv[j]   = lrow[j];
        orow[j] = 0.f;
    }
    __syncthreads();

    for (int t = 0; t < KTOP; t++) {
        float bv = -INFINITY; int bi = 0;
        for (int j = tid; j < NN; j += 256) {
            float x = sv[j];
            if (x > bv) { bv = x; bi = j; }
        }
        rv[tid] = bv; ri[tid] = bi;
        __syncthreads();
#pragma unroll
        for (int s = 128; s > 0; s >>= 1) {
            if (tid < s) {
                float ov = rv[tid + s]; int oi = ri[tid + s];
                if (ov > rv[tid] || (ov == rv[tid] && oi < ri[tid])) {
                    rv[tid] = ov; ri[tid] = oi;
                }
            }
            __syncthreads();
        }
        if (tid == 0) {
            tv[t]  = rv[0];
            tix[t] = ri[0];
            sv[ri[0]] = -INFINITY;   // remove from further consideration
        }
        __syncthreads();
    }

    if (tid == 0) {
        float m = tv[0];             // first pick is the row max
        float e[KTOP];
        float s = 0.f;
#pragma unroll
        for (int t = 0; t < KTOP; t++) { e[t] = expf(tv[t] - m); s += e[t]; }
        float inv = 1.f / s;
#pragma unroll
        for (int t = 0; t < KTOP; t++) orow[tix[t]] = e[t] * inv;
    }
}

// ---------------------------------------------------------------------------
// inputs (metadata order): h[N*D], prior_adj[N*N], W_q[D*D], W_k[D*D],
//                          prior_scale[1]; output: attn[N*N] fp32
// ---------------------------------------------------------------------------
extern "C" void kernel_launch(void* const* d_in, const int* in_sizes, int n_in,
                              void* d_out, int out_size)
{
    const float* h     = (const float*)d_in[0];
    const float* prior = (const float*)d_in[1];
    const float* Wq    = (const float*)d_in[2];
    const float* Wk    = (const float*)d_in[3];
    const float* ps    = (const float*)d_in[4];
    float* out = (float*)d_out;

    const float qscale = 0.04419417382415922f;   // 1/sqrt(512)

    dim3 blk(256);
    proj_kernel<<<dim3(DD / 128, NN / 128), blk>>>(h, Wq, qscale, 0);
    proj_kernel<<<dim3(DD / 128, NN / 128), blk>>>(h, Wk, 1.0f, 1);
    logits_kernel<<<dim3(NN / 128, NN / 128), blk>>>(prior, ps);
    topk_softmax_kernel<<<NN, blk>>>(out);
}

// round 17
// speedup vs baseline: 1.1181x; 1.1181x over previous
#include <cuda_runtime.h>
#include <math.h>

#define NN   8192
#define DD   512
#define KTOP 20
#define BK   16

// Scratch (allocation-free: __device__ globals)
__device__ float g_Q[NN * DD];                 // 16 MB, pre-scaled by 1/sqrt(D)
__device__ float g_Km[NN * DD];                // 16 MB
__device__ float g_logits[(size_t)NN * NN];    // 256 MB

// ---------------------------------------------------------------------------
// NT sgemm, 128x128 tile, BK=16, 256 threads, 8x8 micro-tile, double-buffered
// smem with register prefetch (1 barrier per k-tile).
// MODE 0: C=g_Q  = (h @ Wq^T) * alpha          (alpha = 1/sqrt(D))
// MODE 1: C=g_Km = (h @ Wk^T)
// MODE 2: C=g_logits = g_Q @ g_Km^T + ps*prior, diag = -inf
// ---------------------------------------------------------------------------
template<int MODE>
__global__ __launch_bounds__(256, 2)
void gemm_kernel(const float* __restrict__ Ain, const float* __restrict__ Bin,
                 const float* __restrict__ prior, const float* __restrict__ ps_ptr,
                 float alpha)
{
    const int K  = DD;
    const int Nc = (MODE == 2) ? NN : DD;
    const float* A = (MODE == 2) ? g_Q  : Ain;
    const float* B = (MODE == 2) ? g_Km : Bin;
    float* C = (MODE == 0) ? g_Q : (MODE == 1) ? g_Km : g_logits;

    __shared__ __align__(16) float As[2][BK][128];
    __shared__ __align__(16) float Bs[2][BK][128];

    int tid = threadIdx.x;
    int m0 = blockIdx.y * 128;
    int n0 = blockIdx.x * 128;
    int tr = (tid >> 4) << 3;      // 0..120
    int tc = (tid & 15) << 3;      // 0..120
    int lr = tid >> 2;             // 0..63
    int lk = (tid & 3) << 2;       // 0,4,8,12

    float acc[8][8];
#pragma unroll
    for (int i = 0; i < 8; i++)
#pragma unroll
        for (int j = 0; j < 8; j++) acc[i][j] = 0.f;

    const float* Ap = A + (size_t)(m0 + lr) * K + lk;
    const float* Bp = B + (size_t)(n0 + lr) * K + lk;

    // preload tile 0 -> stage 0
    {
        float4 a0 = *(const float4*)(Ap);
        float4 a1 = *(const float4*)(Ap + (size_t)64 * K);
        float4 b0 = *(const float4*)(Bp);
        float4 b1 = *(const float4*)(Bp + (size_t)64 * K);
        As[0][lk+0][lr]    = a0.x; As[0][lk+1][lr]    = a0.y; As[0][lk+2][lr]    = a0.z; As[0][lk+3][lr]    = a0.w;
        As[0][lk+0][lr+64] = a1.x; As[0][lk+1][lr+64] = a1.y; As[0][lk+2][lr+64] = a1.z; As[0][lk+3][lr+64] = a1.w;
        Bs[0][lk+0][lr]    = b0.x; Bs[0][lk+1][lr]    = b0.y; Bs[0][lk+2][lr]    = b0.z; Bs[0][lk+3][lr]    = b0.w;
        Bs[0][lk+0][lr+64] = b1.x; Bs[0][lk+1][lr+64] = b1.y; Bs[0][lk+2][lr+64] = b1.z; Bs[0][lk+3][lr+64] = b1.w;
    }
    __syncthreads();

    const int NT = K / BK;   // 32
#pragma unroll 1
    for (int t = 0; t < NT; t++) {
        int cur = t & 1;
        float4 na0, na1, nb0, nb1;
        if (t + 1 < NT) {
            int ko = (t + 1) * BK;
            na0 = *(const float4*)(Ap + ko);
            na1 = *(const float4*)(Ap + (size_t)64 * K + ko);
            nb0 = *(const float4*)(Bp + ko);
            nb1 = *(const float4*)(Bp + (size_t)64 * K + ko);
        }
#pragma unroll
        for (int kk = 0; kk < BK; kk++) {
            float4 av0 = *(const float4*)&As[cur][kk][tr];
            float4 av1 = *(const float4*)&As[cur][kk][tr + 4];
            float4 bv0 = *(const float4*)&Bs[cur][kk][tc];
            float4 bv1 = *(const float4*)&Bs[cur][kk][tc + 4];
            float a[8] = {av0.x, av0.y, av0.z, av0.w, av1.x, av1.y, av1.z, av1.w};
            float b[8] = {bv0.x, bv0.y, bv0.z, bv0.w, bv1.x, bv1.y, bv1.z, bv1.w};
#pragma unroll
            for (int i = 0; i < 8; i++)
#pragma unroll
                for (int j = 0; j < 8; j++)
                    acc[i][j] = fmaf(a[i], b[j], acc[i][j]);
        }
        if (t + 1 < NT) {
            int nx = cur ^ 1;
            As[nx][lk+0][lr]    = na0.x; As[nx][lk+1][lr]    = na0.y; As[nx][lk+2][lr]    = na0.z; As[nx][lk+3][lr]    = na0.w;
            As[nx][lk+0][lr+64] = na1.x; As[nx][lk+1][lr+64] = na1.y; As[nx][lk+2][lr+64] = na1.z; As[nx][lk+3][lr+64] = na1.w;
            Bs[nx][lk+0][lr]    = nb0.x; Bs[nx][lk+1][lr]    = nb0.y; Bs[nx][lk+2][lr]    = nb0.z; Bs[nx][lk+3][lr]    = nb0.w;
            Bs[nx][lk+0][lr+64] = nb1.x; Bs[nx][lk+1][lr+64] = nb1.y; Bs[nx][lk+2][lr+64] = nb1.z; Bs[nx][lk+3][lr+64] = nb1.w;
            __syncthreads();
        }
    }

    if (MODE < 2) {
#pragma unroll
        for (int i = 0; i < 8; i++) {
            float* crow = C + (size_t)(m0 + tr + i) * Nc + n0 + tc;
            *(float4*)(crow)     = make_float4(acc[i][0]*alpha, acc[i][1]*alpha, acc[i][2]*alpha, acc[i][3]*alpha);
            *(float4*)(crow + 4) = make_float4(acc[i][4]*alpha, acc[i][5]*alpha, acc[i][6]*alpha, acc[i][7]*alpha);
        }
    } else {
        float ps = *ps_ptr;
#pragma unroll
        for (int i = 0; i < 8; i++) {
            int r = m0 + tr + i;
            const float* prow = prior + (size_t)r * NN + n0 + tc;
            float*       lrow = C     + (size_t)r * NN + n0 + tc;
            float4 p0 = *(const float4*)(prow);
            float4 p1 = *(const float4*)(prow + 4);
            float v[8];
            v[0] = fmaf(ps, p0.x, acc[i][0]);
            v[1] = fmaf(ps, p0.y, acc[i][1]);
            v[2] = fmaf(ps, p0.z, acc[i][2]);
            v[3] = fmaf(ps, p0.w, acc[i][3]);
            v[4] = fmaf(ps, p1.x, acc[i][4]);
            v[5] = fmaf(ps, p1.y, acc[i][5]);
            v[6] = fmaf(ps, p1.z, acc[i][6]);
            v[7] = fmaf(ps, p1.w, acc[i][7]);
            int dj = r - (n0 + tc);
            if (dj >= 0 && dj < 8) v[dj] = -INFINITY;
            *(float4*)(lrow)     = make_float4(v[0], v[1], v[2], v[3]);
            *(float4*)(lrow + 4) = make_float4(v[4], v[5], v[6], v[7]);
        }
    }
}

// ---------------------------------------------------------------------------
// Tournament top-k + softmax. One CTA per row.
// Thread t owns the strided segment {j : j % 256 == t} (bank-conflict free).
// Each thread keeps its segment max in registers; per extraction round only
// the winning thread rescans its 32 elements. 2 barriers per round.
// ---------------------------------------------------------------------------
__global__ __launch_bounds__(256)
void topk_softmax_kernel(float* __restrict__ out)
{
    __shared__ __align__(16) float sv[NN];
    __shared__ float wval[8];
    __shared__ int   warg[8];
    __shared__ float tv[KTOP];
    __shared__ int   tix[KTOP];
    __shared__ int   winner;

    int row = blockIdx.x;
    int tid = threadIdx.x;
    const float4* l4 = (const float4*)(g_logits + (size_t)row * NN);
    float4*       o4 = (float4*)(out + (size_t)row * NN);
    float*        orow = out + (size_t)row * NN;

    // stage row into smem; zero the (poisoned) output row
    float4 z4 = make_float4(0.f, 0.f, 0.f, 0.f);
#pragma unroll
    for (int q = tid; q < NN / 4; q += 256) {
        ((float4*)sv)[q] = l4[q];
        o4[q] = z4;
    }
    __syncthreads();

    // per-thread segment max (stride-256 ownership: conflict-free LDS)
    float mv = -INFINITY; int mi = tid;
#pragma unroll
    for (int k = 0; k < NN / 256; k++) {
        int j = tid + (k << 8);
        float x = sv[j];
        if (x > mv) { mv = x; mi = j; }
    }

    for (int t = 0; t < KTOP; t++) {
        // block argmax of the 256 register-resident (mv, mi)
        float v = mv; int ix = mi;
#pragma unroll
        for (int o = 16; o > 0; o >>= 1) {
            float ov = __shfl_down_sync(0xffffffffu, v, o);
            int   oi = __shfl_down_sync(0xffffffffu, ix, o);
            if (ov > v || (ov == v && oi < ix)) { v = ov; ix = oi; }
        }
        if ((tid & 31) == 0) { wval[tid >> 5] = v; warg[tid >> 5] = ix; }
        __syncthreads();
        if (tid == 0) {
            float bv = wval[0]; int bi = warg[0];
#pragma unroll
            for (int w = 1; w < 8; w++) {
                float ov = wval[w]; int oi = warg[w];
                if (ov > bv || (ov == bv && oi < bi)) { bv = ov; bi = oi; }
            }
            tv[t] = bv; tix[t] = bi; winner = bi;
        }
        __syncthreads();
        int wi = winner;
        if ((wi & 255) == tid) {           // owner removes & rescans its segment
            sv[wi] = -INFINITY;
            float nv = -INFINITY; int ni = tid;
#pragma unroll
            for (int k = 0; k < NN / 256; k++) {
                int j = tid + (k << 8);
                float x = sv[j];
                if (x > nv) { nv = x; ni = j; }
            }
            mv = nv; mi = ni;
        }
        // no barrier needed: each thread only reads its OWN (mv,mi) next round
    }

    if (tid == 0) {
        float m = tv[0];                   // first extraction is the row max
        float e[KTOP];
        float s = 0.f;
#pragma unroll
        for (int t = 0; t < KTOP; t++) { e[t] = expf(tv[t] - m); s += e[t]; }
        float inv = 1.f / s;
#pragma unroll
        for (int t = 0; t < KTOP; t++) orow[tix[t]] = e[t] * inv;
    }
}

// ---------------------------------------------------------------------------
// inputs (metadata order): h[N*D], prior_adj[N*N], W_q[D*D], W_k[D*D],
//                          prior_scale[1]; output: attn[N*N] fp32
// ---------------------------------------------------------------------------
extern "C" void kernel_launch(void* const* d_in, const int* in_sizes, int n_in,
                              void* d_out, int out_size)
{
    const float* h     = (const float*)d_in[0];
    const float* prior = (const float*)d_in[1];
    const float* Wq    = (const float*)d_in[2];
    const float* Wk    = (const float*)d_in[3];
    const float* ps    = (const float*)d_in[4];
    float* out = (float*)d_out;

    const float qscale = 0.04419417382415922f;   // 1/sqrt(512)

    dim3 blk(256);
    gemm_kernel<0><<<dim3(DD / 128, NN / 128), blk>>>(h, Wq, nullptr, nullptr, qscale);
    gemm_kernel<1><<<dim3(DD / 128, NN / 128), blk>>>(h, Wk, nullptr, nullptr, 1.0f);
    gemm_kernel<2><<<dim3(NN / 128, NN / 128), blk>>>(nullptr, nullptr, prior, ps, 1.0f);
    topk_softmax_kernel<<<NN, blk>>>(out);
}